// round 8
// baseline (speedup 1.0000x reference)
#include <cuda_runtime.h>
#include <cuda_bf16.h>
#include <cstdint>

#define FDIM    128
#define TP      64
#define NTHR    128
#define NLAYERS 8
#define NGEMM   16
#define OMEGA_W 30.0f
#define SKEW_CYC 1800u

// ---------------- smem layout (bytes) ----------------
#define SMEM_CS     0        // 64*3 floats coords (768 B)
#define SMEM_YB     1024     // [4][64] floats (1 KB)
#define SMEM_X      2048     // X: hi 16K + lo 16K (32 KB)
#define SMEM_W      34816    // 4 warps x 8 stages x 2KB (64 KB)
#define SMEM_TOTAL  100352

// Chunked weights: chunk c = g*8+kk is 8 KB: hi[128 f][16 kc] (4KB) then lo (4KB).
__device__ __align__(16) __nv_bfloat16 g_Wc[NGEMM * 8 * 2 * FDIM * 16];

// ---------------- PTX helpers ----------------
__device__ __forceinline__ uint32_t smem_u32(const void* p) {
    uint32_t a;
    asm("{ .reg .u64 t; cvta.to.shared.u64 t, %1; cvt.u32.u64 %0, t; }" : "=r"(a) : "l"(p));
    return a;
}
__device__ __forceinline__ void cp16(uint32_t dst, const void* src) {
    asm volatile("cp.async.cg.shared.global [%0], [%1], 16;" :: "r"(dst), "l"(src));
}
#define CP_COMMIT() asm volatile("cp.async.commit_group;" ::: "memory")
#define CP_WAIT7()  asm volatile("cp.async.wait_group 7;" ::: "memory")

#define LDSM_X4(r, addr) \
    asm volatile("ldmatrix.sync.aligned.m8n8.x4.shared.b16 {%0,%1,%2,%3}, [%4];" \
        : "=r"((r)[0]), "=r"((r)[1]), "=r"((r)[2]), "=r"((r)[3]) : "r"(addr))
#define LDSM_X4T(r, addr) \
    asm volatile("ldmatrix.sync.aligned.m8n8.x4.trans.shared.b16 {%0,%1,%2,%3}, [%4];" \
        : "=r"((r)[0]), "=r"((r)[1]), "=r"((r)[2]), "=r"((r)[3]) : "r"(addr))

#define MMA16816(d, a, b0, b1) \
    asm volatile("mma.sync.aligned.m16n8k16.row.col.f32.bf16.bf16.f32 " \
        "{%0,%1,%2,%3},{%4,%5,%6,%7},{%8,%9},{%0,%1,%2,%3};" \
        : "+f"((d)[0]), "+f"((d)[1]), "+f"((d)[2]), "+f"((d)[3]) \
        : "r"((a)[0]), "r"((a)[1]), "r"((a)[2]), "r"((a)[3]), "r"(b0), "r"(b1))

// W chunk slice (per warp): rows 32 B (16 bf16); 16B-unit XOR keeps the 8 rows
// of every ldmatrix 8x8 fetch in 8 distinct bank groups.
__device__ __forceinline__ uint32_t wchunk_off(int r, int u) {
    return (uint32_t)(r * 32 + ((u << 4) ^ (((r >> 2) & 1) << 4)));
}
// Activation tile: rows 128 B (64 bf16), XOR swizzle
__device__ __forceinline__ uint32_t xo64(int f, int n) {
    return (uint32_t)(f * 128 + ((2 * n) ^ ((f & 7) << 4)));
}
__device__ __forceinline__ void store_split64(char* xb, int f, int n, float v0, float v1) {
    uint32_t off = xo64(f, n);
    __nv_bfloat162 hi = __floats2bfloat162_rn(v0, v1);
    float r0 = v0 - __low2float(hi);
    float r1 = v1 - __high2float(hi);
    __nv_bfloat162 lo = __floats2bfloat162_rn(r0, r1);
    *reinterpret_cast<__nv_bfloat162*>(xb + off) = hi;
    *reinterpret_cast<__nv_bfloat162*>(xb + 16384 + off) = lo;
}

// ---------------- weight prep: fp32 -> split bf16 hi/lo, chunked ----------------
__global__ void prep_weights_kernel(const float* __restrict__ W1,
                                    const float* __restrict__ W2) {
    int g = blockIdx.x;
    int layer = g >> 1;
    const float* src = ((g & 1) ? W2 : W1) + layer * FDIM * FDIM;
    for (int idx = threadIdx.x; idx < FDIM * FDIM; idx += blockDim.x) {
        int f = idx >> 7;
        int k = idx & 127;
        float w = src[idx];
        __nv_bfloat16 hi = __float2bfloat16(w);
        __nv_bfloat16 lo = __float2bfloat16(w - __bfloat162float(hi));
        int c = g * 8 + (k >> 4);
        int kc = k & 15;
        size_t base = (size_t)c * 4096;          // elems per chunk
        g_Wc[base + f * 16 + kc] = hi;
        g_Wc[base + 2048 + f * 16 + kc] = lo;
    }
}

// ---------------- main kernel ----------------
__global__ __launch_bounds__(NTHR, 2)
void siren_mma_kernel(const float* __restrict__ coords,
                      const float* __restrict__ W_first,
                      const float* __restrict__ b_first,
                      const float* __restrict__ b1,
                      const float* __restrict__ b2,
                      const float* __restrict__ W_out,
                      const float* __restrict__ b_out,
                      float* __restrict__ out, int N) {
    extern __shared__ char smem[];
    const uint32_t sb = smem_u32(smem);
    float* cs = (float*)(smem + SMEM_CS);

    const int tid  = threadIdx.x;
    const int w    = tid >> 5;
    const int lane = tid & 31;
    const int f0   = w << 5;               // warp owns features [32w, 32w+32)
    const int tg   = lane >> 2;
    const int t4   = lane & 3;
    const int li   = lane >> 3;
    const int lr   = lane & 7;
    const int P0   = blockIdx.x * TP;

    char* xb = smem + SMEM_X;
    const uint32_t xbu = sb + SMEM_X;
    const uint32_t wbu = sb + SMEM_W + w * 16384;     // this warp's W ring
    const char* gw = (const char*)g_Wc;

    // per-warp chunk issue: chunk c -> stage c&7 of this warp's ring
    auto issue_chunk = [&](int c) {
        const char* srch = gw + (size_t)c * 8192 + (f0 + lane) * 32;
        uint32_t dst = wbu + ((uint32_t)(c & 7) << 11) + ((uint32_t)lane << 5);
        uint32_t sw = ((uint32_t)(lane >> 2) & 1) << 4;
        cp16(dst + (0u ^ sw), srch);
        cp16(dst + (16u ^ sw), srch + 16);
        cp16(dst + 1024u + (0u ^ sw), srch + 4096);
        cp16(dst + 1024u + (16u ^ sw), srch + 4096 + 16);
        CP_COMMIT();
    };

    // prologue: prefetch chunks 0..7 (covers GEMM 0)
#pragma unroll
    for (int c = 0; c < 8; c++) issue_chunk(c);

    // stage coords [p][3]
    for (int t = tid; t < 3 * TP; t += NTHR) {
        int p = t / 3, d = t - p * 3;
        int pg = min(P0 + p, N - 1);
        cs[t] = coords[pg * 3 + d];
    }
    __syncthreads();

    // rows this thread owns: f0 + 16*mi + tg (+8)
    float h[2][8][4];

    // ---- first layer ----
#pragma unroll
    for (int mi = 0; mi < 2; mi++) {
        const int ra = f0 + 16 * mi + tg, rb = ra + 8;
        const float wa0 = __ldg(&W_first[ra * 3]), wa1 = __ldg(&W_first[ra * 3 + 1]),
                    wa2 = __ldg(&W_first[ra * 3 + 2]);
        const float wb0 = __ldg(&W_first[rb * 3]), wb1 = __ldg(&W_first[rb * 3 + 1]),
                    wb2 = __ldg(&W_first[rb * 3 + 2]);
        const float ba = __ldg(&b_first[ra]), bb = __ldg(&b_first[rb]);
#pragma unroll
        for (int ni = 0; ni < 8; ni++) {
            const int nl = 8 * ni + t4 * 2;
            float x0 = cs[nl * 3], y0 = cs[nl * 3 + 1], z0 = cs[nl * 3 + 2];
            float x1 = cs[nl * 3 + 3], y1 = cs[nl * 3 + 4], z1 = cs[nl * 3 + 5];
            h[mi][ni][0] = __sinf(OMEGA_W * fmaf(wa0, x0, fmaf(wa1, y0, fmaf(wa2, z0, ba))));
            h[mi][ni][1] = __sinf(OMEGA_W * fmaf(wa0, x1, fmaf(wa1, y1, fmaf(wa2, z1, ba))));
            h[mi][ni][2] = __sinf(OMEGA_W * fmaf(wb0, x0, fmaf(wb1, y0, fmaf(wb2, z0, bb))));
            h[mi][ni][3] = __sinf(OMEGA_W * fmaf(wb0, x1, fmaf(wb1, y1, fmaf(wb2, z1, bb))));
            store_split64(xb, ra, nl, h[mi][ni][0], h[mi][ni][1]);
            store_split64(xb, rb, nl, h[mi][ni][2], h[mi][ni][3]);
        }
    }
    __syncthreads();

    // anti-phase insurance for the co-resident CTA pair (classic placement maps
    // bids b and b+148 to the same SM; skew one of them by ~half an epilogue).
    if (((blockIdx.x / 148) & 1) != 0) {
        uint32_t t0, t1;
        asm volatile("mov.u32 %0, %%clock;" : "=r"(t0));
        do { asm volatile("mov.u32 %0, %%clock;" : "=r"(t1)); } while (t1 - t0 < SKEW_CYC);
    }

    for (int g = 0; g < NGEMM; g++) {
        const int layer = g >> 1;
        const bool even = ((g & 1) == 0);

        float d[2][8][4];
#pragma unroll
        for (int mi = 0; mi < 2; mi++)
#pragma unroll
            for (int ni = 0; ni < 8; ni++)
                d[mi][ni][0] = d[mi][ni][1] = d[mi][ni][2] = d[mi][ni][3] = 0.f;

#pragma unroll
        for (int kk = 0; kk < 8; kk++) {
            CP_WAIT7();                               // chunk g*8+kk resident (stage kk)
            const uint32_t wstage = wbu + ((uint32_t)kk << 11);
            uint32_t ahi[2][4], alo[2][4];
#pragma unroll
            for (int mi = 0; mi < 2; mi++) {
                const int r = 16 * mi + ((li & 1) << 3) + lr;
                const uint32_t aoff = wchunk_off(r, li >> 1);
                LDSM_X4(ahi[mi], wstage + aoff);
                LDSM_X4(alo[mi], wstage + 1024u + aoff);
            }
            const int krow = (kk << 4) + ((li & 1) << 3) + lr;
            uint32_t bh[4][4], bl[4][4];
#pragma unroll
            for (int q = 0; q < 4; q++) {
                const int ncol = q * 16 + ((li >> 1) << 3);
                const uint32_t boff = xo64(krow, ncol);
                LDSM_X4T(bh[q], xbu + boff);
                LDSM_X4T(bl[q], xbu + 16384u + boff);
            }
            // stream next chunk into the stage just consumed (wraps harmlessly at end)
            issue_chunk((g * 8 + kk + 8) & 127);

#pragma unroll
            for (int mi = 0; mi < 2; mi++)
#pragma unroll
                for (int q = 0; q < 4; q++) {
                    MMA16816(d[mi][2 * q],     ahi[mi], bh[q][0], bh[q][1]);
                    MMA16816(d[mi][2 * q + 1], ahi[mi], bh[q][2], bh[q][3]);
                }
#pragma unroll
            for (int mi = 0; mi < 2; mi++)
#pragma unroll
                for (int q = 0; q < 4; q++) {
                    MMA16816(d[mi][2 * q],     ahi[mi], bl[q][0], bl[q][1]);
                    MMA16816(d[mi][2 * q + 1], ahi[mi], bl[q][2], bl[q][3]);
                }
#pragma unroll
            for (int mi = 0; mi < 2; mi++)
#pragma unroll
                for (int q = 0; q < 4; q++) {
                    MMA16816(d[mi][2 * q],     alo[mi], bh[q][0], bh[q][1]);
                    MMA16816(d[mi][2 * q + 1], alo[mi], bh[q][2], bh[q][3]);
                }
        }

        __syncthreads();   // all warps done reading X

        if (g < NGEMM - 1) {
            // ---- epilogue: write X in place ----
#pragma unroll
            for (int mi = 0; mi < 2; mi++) {
                const int ra = f0 + 16 * mi + tg, rb = ra + 8;
                float ba, bb;
                if (even) {
                    ba = __ldg(&b1[layer * FDIM + ra]);
                    bb = __ldg(&b1[layer * FDIM + rb]);
                } else {
                    ba = __ldg(&b2[layer * FDIM + ra]);
                    bb = __ldg(&b2[layer * FDIM + rb]);
                }
                const float w_in = (even && layer > 0) ? 0.5f : 1.0f;
#pragma unroll
                for (int ni = 0; ni < 8; ni++) {
                    const int nl = 8 * ni + t4 * 2;
                    if (even) {
                        float s00 = __sinf(OMEGA_W * fmaf(w_in, d[mi][ni][0], ba));
                        float s01 = __sinf(OMEGA_W * fmaf(w_in, d[mi][ni][1], ba));
                        float s10 = __sinf(OMEGA_W * fmaf(w_in, d[mi][ni][2], bb));
                        float s11 = __sinf(OMEGA_W * fmaf(w_in, d[mi][ni][3], bb));
                        store_split64(xb, ra, nl, s00, s01);
                        store_split64(xb, rb, nl, s10, s11);
                    } else {
                        h[mi][ni][0] += __sinf(OMEGA_W * (d[mi][ni][0] + ba));
                        h[mi][ni][1] += __sinf(OMEGA_W * (d[mi][ni][1] + ba));
                        h[mi][ni][2] += __sinf(OMEGA_W * (d[mi][ni][2] + bb));
                        h[mi][ni][3] += __sinf(OMEGA_W * (d[mi][ni][3] + bb));
                        store_split64(xb, ra, nl, h[mi][ni][0], h[mi][ni][1]);
                        store_split64(xb, rb, nl, h[mi][ni][2], h[mi][ni][3]);
                    }
                }
            }
            __syncthreads();   // epilogue writes visible before next GEMM's LDSM
        } else {
            // ---- final epilogue: h = 0.5*(h+s2), output GEMV ----
            float* ybuf = (float*)(smem + SMEM_YB);
            float p0s[8], p1s[8];
#pragma unroll
            for (int ni = 0; ni < 8; ni++) { p0s[ni] = 0.f; p1s[ni] = 0.f; }
#pragma unroll
            for (int mi = 0; mi < 2; mi++) {
                const int ra = f0 + 16 * mi + tg, rb = ra + 8;
                const float ba = __ldg(&b2[layer * FDIM + ra]);
                const float bb = __ldg(&b2[layer * FDIM + rb]);
                const float woa = __ldg(&W_out[ra]), wob = __ldg(&W_out[rb]);
#pragma unroll
                for (int ni = 0; ni < 8; ni++) {
                    float h0 = 0.5f * (h[mi][ni][0] + __sinf(OMEGA_W * (d[mi][ni][0] + ba)));
                    float h1 = 0.5f * (h[mi][ni][1] + __sinf(OMEGA_W * (d[mi][ni][1] + ba)));
                    float h2 = 0.5f * (h[mi][ni][2] + __sinf(OMEGA_W * (d[mi][ni][2] + bb)));
                    float h3 = 0.5f * (h[mi][ni][3] + __sinf(OMEGA_W * (d[mi][ni][3] + bb)));
                    p0s[ni] += fmaf(h0, woa, h2 * wob);
                    p1s[ni] += fmaf(h1, woa, h3 * wob);
                }
            }
#pragma unroll
            for (int ni = 0; ni < 8; ni++) {
                float p0 = p0s[ni], p1 = p1s[ni];
#pragma unroll
                for (int m = 4; m <= 16; m <<= 1) {
                    p0 += __shfl_xor_sync(0xffffffffu, p0, m);
                    p1 += __shfl_xor_sync(0xffffffffu, p1, m);
                }
                if (tg == 0) {
                    int nl = 8 * ni + t4 * 2;
                    *reinterpret_cast<float2*>(&ybuf[w * TP + nl]) = make_float2(p0, p1);
                }
            }
            __syncthreads();
        }
    }

    // ---- cross-warp output reduction ----
    if (tid < TP) {
        int p = tid;
        if (P0 + p < N) {
            float* ybuf = (float*)(smem + SMEM_YB);
            float y = __ldg(&b_out[0]) + ybuf[p] + ybuf[TP + p]
                    + ybuf[2 * TP + p] + ybuf[3 * TP + p];
            out[P0 + p] = y;
        }
    }
}

extern "C" void kernel_launch(void* const* d_in, const int* in_sizes, int n_in,
                              void* d_out, int out_size) {
    const float* coords  = (const float*)d_in[0];
    const float* W_first = (const float*)d_in[1];
    const float* b_first = (const float*)d_in[2];
    const float* W1      = (const float*)d_in[3];
    const float* b1      = (const float*)d_in[4];
    const float* W2      = (const float*)d_in[5];
    const float* b2      = (const float*)d_in[6];
    const float* W_out   = (const float*)d_in[7];
    const float* b_out   = (const float*)d_in[8];
    const int N = in_sizes[0] / 3;

    prep_weights_kernel<<<NGEMM, 256>>>(W1, W2);

    cudaFuncSetAttribute(siren_mma_kernel,
                         cudaFuncAttributeMaxDynamicSharedMemorySize, SMEM_TOTAL);

    const int nblocks = (N + TP - 1) / TP;
    siren_mma_kernel<<<nblocks, NTHR, SMEM_TOTAL>>>(coords, W_first, b_first,
                                                    b1, b2, W_out, b_out,
                                                    (float*)d_out, N);
}

// round 9
// speedup vs baseline: 2.2653x; 2.2653x over previous
#include <cuda_runtime.h>
#include <cuda_fp16.h>
#include <cstdint>

#define FDIM    128
#define TP      128
#define NTHR    256
#define NLAYERS 8
#define NGEMM   16
#define OMEGA_W 30.0f
#define SKEW_CYC 1300u

// ---------------- smem layout (bytes) ----------------
#define SMEM_MB_W0   0
#define SMEM_MB_W1   8
#define SMEM_CNT     16                    // 16 int counters
#define SMEM_CS      128                   // 128*3 floats coords (1536 B)
#define SMEM_YBUF    2048                  // [2][4][64] floats (2 KB)
#define SMEM_X       4096                  // X half0 16K, half1 16K (fp16)
#define SMEM_WBUF0   36864                 // weight buf 0 (32 KB fp16)
#define SMEM_WBUF1   69632                 // weight buf 1
#define SMEM_TOTAL   102400

// Pre-converted, pre-swizzled fp16 weights: [gemm][128*128]
__device__ __align__(128) __half g_W[NGEMM][FDIM * FDIM];

// ---------------- PTX helpers ----------------
__device__ __forceinline__ uint32_t smem_u32(const void* p) {
    uint32_t a;
    asm("{ .reg .u64 t; cvta.to.shared.u64 t, %1; cvt.u32.u64 %0, t; }" : "=r"(a) : "l"(p));
    return a;
}
#define MBAR_INIT(mbar, cnt) \
    asm volatile("mbarrier.init.shared.b64 [%0], %1;" :: "r"(mbar), "r"(cnt) : "memory")
#define MBAR_EXPECT_TX(mbar, bytes) \
    asm volatile("mbarrier.arrive.expect_tx.shared.b64 _, [%0], %1;" :: "r"(mbar), "r"(bytes) : "memory")
#define MBAR_WAIT(mbar, ph) do {                                              \
    asm volatile("{\n\t.reg .pred P1;\n\t"                                    \
        "WL_%=:\n\t"                                                          \
        "mbarrier.try_wait.parity.acquire.cta.shared::cta.b64 P1, [%0], %1, 0x989680;\n\t" \
        "@P1 bra.uni WD_%=;\n\t"                                              \
        "bra.uni WL_%=;\n\t"                                                  \
        "WD_%=:\n\t}"                                                         \
        :: "r"(mbar), "r"(ph) : "memory");                                    \
} while (0)
#define BULK_G2S(dst, src, bytes, mbar) \
    asm volatile("cp.async.bulk.shared::cluster.global.mbarrier::complete_tx::bytes [%0], [%1], %2, [%3];" \
        :: "r"(dst), "l"(src), "r"(bytes), "r"(mbar) : "memory")
#define BAR_HALF(id) asm volatile("bar.sync %0, 128;" :: "r"(id) : "memory")

#define LDSM_X4(r, addr) \
    asm volatile("ldmatrix.sync.aligned.m8n8.x4.shared.b16 {%0,%1,%2,%3}, [%4];" \
        : "=r"((r)[0]), "=r"((r)[1]), "=r"((r)[2]), "=r"((r)[3]) : "r"(addr))
#define LDSM_X4T(r, addr) \
    asm volatile("ldmatrix.sync.aligned.m8n8.x4.trans.shared.b16 {%0,%1,%2,%3}, [%4];" \
        : "=r"((r)[0]), "=r"((r)[1]), "=r"((r)[2]), "=r"((r)[3]) : "r"(addr))

#define MMA16816(d, a, b0, b1) \
    asm volatile("mma.sync.aligned.m16n8k16.row.col.f32.f16.f16.f32 " \
        "{%0,%1,%2,%3},{%4,%5,%6,%7},{%8,%9},{%0,%1,%2,%3};" \
        : "+f"((d)[0]), "+f"((d)[1]), "+f"((d)[2]), "+f"((d)[3]) \
        : "r"((a)[0]), "r"((a)[1]), "r"((a)[2]), "r"((a)[3]), "r"(b0), "r"(b1))

// Weight tile: rows 256 B (128 fp16), XOR swizzle
__device__ __forceinline__ uint32_t woff(int f, int k) {
    return (uint32_t)(f * 256 + ((2 * k) ^ ((f & 7) << 4)));
}
// Activation half-tile: rows 128 B (64 fp16), XOR swizzle
__device__ __forceinline__ uint32_t xo64(int f, int n) {
    return (uint32_t)(f * 128 + ((2 * n) ^ ((f & 7) << 4)));
}
__device__ __forceinline__ void store_h16(char* xb, int f, int n, float v0, float v1) {
    *reinterpret_cast<__half2*>(xb + xo64(f, n)) = __floats2half2_rn(v0, v1);
}

// ---------------- weight prep: fp32 -> fp16, swizzled ----------------
__global__ void prep_weights_kernel(const float* __restrict__ W1,
                                    const float* __restrict__ W2) {
    int g = blockIdx.x;
    int layer = g >> 1;
    const float* src = ((g & 1) ? W2 : W1) + layer * FDIM * FDIM;
    for (int idx = threadIdx.x; idx < FDIM * FDIM; idx += blockDim.x) {
        int f = idx >> 7;
        int k = idx & 127;
        g_W[g][f * FDIM + (k ^ ((f & 7) << 3))] = __float2half_rn(src[idx]);
    }
}

// ---------------- main kernel ----------------
__global__ __launch_bounds__(NTHR, 1)
void siren_mma_kernel(const float* __restrict__ coords,
                      const float* __restrict__ W_first,
                      const float* __restrict__ b_first,
                      const float* __restrict__ b1,
                      const float* __restrict__ b2,
                      const float* __restrict__ W_out,
                      const float* __restrict__ b_out,
                      float* __restrict__ out, int N) {
    extern __shared__ char smem[];
    const uint32_t sb = smem_u32(smem);
    float* cs = (float*)(smem + SMEM_CS);
    int* cnt = (int*)(smem + SMEM_CNT);

    const int tid  = threadIdx.x;
    const int w    = tid >> 5;
    const int lane = tid & 31;
    const int wm   = w & 3;                // M group: features [32*wm, 32*wm+32)
    const int hf   = w >> 2;               // point half 0/1
    const int f0   = wm << 5;
    const int n0   = hf << 6;
    const int tg   = lane >> 2;
    const int t4   = lane & 3;
    const int li   = lane >> 3;
    const int lr   = lane & 7;
    const int P0   = blockIdx.x * TP;
    const int barid = 1 + hf;

    char* xb = smem + SMEM_X + hf * 16384;
    const uint32_t xbu = sb + SMEM_X + hf * 16384;

    if (tid == 0) {
        MBAR_INIT(sb + SMEM_MB_W0, 1);
        MBAR_INIT(sb + SMEM_MB_W1, 1);
    }
    if (tid < NGEMM) cnt[tid] = 0;
    for (int t = tid; t < 3 * TP; t += NTHR) {
        int p = t / 3, d = t - p * 3;
        int pg = min(P0 + p, N - 1);
        cs[t] = coords[pg * 3 + d];
    }
    __syncthreads();

    if (tid == 0) {
        MBAR_EXPECT_TX(sb + SMEM_MB_W0, 32768u);
        BULK_G2S(sb + SMEM_WBUF0, (const void*)&g_W[0][0], 32768u, sb + SMEM_MB_W0);
        MBAR_EXPECT_TX(sb + SMEM_MB_W1, 32768u);
        BULK_G2S(sb + SMEM_WBUF1, (const void*)&g_W[1][0], 32768u, sb + SMEM_MB_W1);
    }

    // rows this thread owns: f0 + 16*mi + tg (+8)
    float h[2][8][4];

    // ---- first layer (fp32) ----
#pragma unroll
    for (int mi = 0; mi < 2; mi++) {
        const int ra = f0 + 16 * mi + tg, rb = ra + 8;
        const float wa0 = __ldg(&W_first[ra * 3]), wa1 = __ldg(&W_first[ra * 3 + 1]),
                    wa2 = __ldg(&W_first[ra * 3 + 2]);
        const float wb0 = __ldg(&W_first[rb * 3]), wb1 = __ldg(&W_first[rb * 3 + 1]),
                    wb2 = __ldg(&W_first[rb * 3 + 2]);
        const float ba = __ldg(&b_first[ra]), bb = __ldg(&b_first[rb]);
#pragma unroll
        for (int ni = 0; ni < 8; ni++) {
            const int nl = 8 * ni + t4 * 2;
            const int p = n0 + nl;
            float x0 = cs[p * 3], y0 = cs[p * 3 + 1], z0 = cs[p * 3 + 2];
            float x1 = cs[p * 3 + 3], y1 = cs[p * 3 + 4], z1 = cs[p * 3 + 5];
            h[mi][ni][0] = __sinf(OMEGA_W * fmaf(wa0, x0, fmaf(wa1, y0, fmaf(wa2, z0, ba))));
            h[mi][ni][1] = __sinf(OMEGA_W * fmaf(wa0, x1, fmaf(wa1, y1, fmaf(wa2, z1, ba))));
            h[mi][ni][2] = __sinf(OMEGA_W * fmaf(wb0, x0, fmaf(wb1, y0, fmaf(wb2, z0, bb))));
            h[mi][ni][3] = __sinf(OMEGA_W * fmaf(wb0, x1, fmaf(wb1, y1, fmaf(wb2, z1, bb))));
            store_h16(xb, ra, nl, h[mi][ni][0], h[mi][ni][1]);
            store_h16(xb, rb, nl, h[mi][ni][2], h[mi][ni][3]);
        }
    }
    BAR_HALF(barid);

    // anti-phase skew: half 1 delayed ~one epilogue. With 1-product MMA the
    // epilogue (MUFU) and MMA (tensor) are rate-matched on disjoint pipes, so
    // anti-phased halves keep both pipes busy simultaneously.
    if (hf == 1) {
        uint32_t t0, t1;
        asm volatile("mov.u32 %0, %%clock;" : "=r"(t0));
        do { asm volatile("mov.u32 %0, %%clock;" : "=r"(t1)); } while (t1 - t0 < SKEW_CYC);
    }

    int wph0 = 0, wph1 = 0;

    for (int g = 0; g < NGEMM; g++) {
        const int layer = g >> 1;
        const bool even = ((g & 1) == 0);

        {   // wait for this GEMM's weight buffer
            uint32_t mb = sb + ((g & 1) ? SMEM_MB_W1 : SMEM_MB_W0);
            int ph = (g & 1) ? wph1 : wph0;
            MBAR_WAIT(mb, ph);
            if (g & 1) wph1 ^= 1; else wph0 ^= 1;
        }

        const uint32_t wbase = sb + ((g & 1) ? SMEM_WBUF1 : SMEM_WBUF0);

        float d[2][8][4];
#pragma unroll
        for (int mi = 0; mi < 2; mi++)
#pragma unroll
            for (int ni = 0; ni < 8; ni++)
                d[mi][ni][0] = d[mi][ni][1] = d[mi][ni][2] = d[mi][ni][3] = 0.f;

        // ---- single-product fp16 MMA ----
#pragma unroll
        for (int kk = 0; kk < 8; kk++) {
            const int k0 = kk << 4;
            uint32_t a[2][4];
#pragma unroll
            for (int mi = 0; mi < 2; mi++) {
                const int arow = f0 + 16 * mi + ((li & 1) << 3) + lr;
                const int acol = k0 + ((li >> 1) << 3);
                LDSM_X4(a[mi], wbase + woff(arow, acol));
            }
            const int krow = k0 + ((li & 1) << 3) + lr;
            uint32_t b[4][4];
#pragma unroll
            for (int q = 0; q < 4; q++) {
                const int ncol = q * 16 + ((li >> 1) << 3);
                LDSM_X4T(b[q], xbu + xo64(krow, ncol));
            }
#pragma unroll
            for (int mi = 0; mi < 2; mi++)
#pragma unroll
                for (int q = 0; q < 4; q++) {
                    MMA16816(d[mi][2 * q],     a[mi], b[q][0], b[q][1]);
                    MMA16816(d[mi][2 * q + 1], a[mi], b[q][2], b[q][3]);
                }
        }

        // W(g) consumption tracking; last warp launches prefetch of g+2
        if (lane == 0) {
            int old = atomicAdd(&cnt[g], 1);
            if (old == 7 && g + 2 < NGEMM) {
                uint32_t mb = sb + ((g & 1) ? SMEM_MB_W1 : SMEM_MB_W0);
                uint32_t wbuf = sb + ((g & 1) ? SMEM_WBUF1 : SMEM_WBUF0);
                MBAR_EXPECT_TX(mb, 32768u);
                BULK_G2S(wbuf, (const void*)&g_W[g + 2][0], 32768u, mb);
            }
        }

        BAR_HALF(barid);   // this half done reading its X

        if (g < NGEMM - 1) {
            // ---- epilogue: write X-half in place ----
#pragma unroll
            for (int mi = 0; mi < 2; mi++) {
                const int ra = f0 + 16 * mi + tg, rb = ra + 8;
                float ba, bb;
                if (even) {
                    ba = __ldg(&b1[layer * FDIM + ra]);
                    bb = __ldg(&b1[layer * FDIM + rb]);
                } else {
                    ba = __ldg(&b2[layer * FDIM + ra]);
                    bb = __ldg(&b2[layer * FDIM + rb]);
                }
                const float w_in = (even && layer > 0) ? 0.5f : 1.0f;
#pragma unroll
                for (int ni = 0; ni < 8; ni++) {
                    const int nl = 8 * ni + t4 * 2;
                    if (even) {
                        float s00 = __sinf(OMEGA_W * fmaf(w_in, d[mi][ni][0], ba));
                        float s01 = __sinf(OMEGA_W * fmaf(w_in, d[mi][ni][1], ba));
                        float s10 = __sinf(OMEGA_W * fmaf(w_in, d[mi][ni][2], bb));
                        float s11 = __sinf(OMEGA_W * fmaf(w_in, d[mi][ni][3], bb));
                        store_h16(xb, ra, nl, s00, s01);
                        store_h16(xb, rb, nl, s10, s11);
                    } else {
                        h[mi][ni][0] += __sinf(OMEGA_W * (d[mi][ni][0] + ba));
                        h[mi][ni][1] += __sinf(OMEGA_W * (d[mi][ni][1] + ba));
                        h[mi][ni][2] += __sinf(OMEGA_W * (d[mi][ni][2] + bb));
                        h[mi][ni][3] += __sinf(OMEGA_W * (d[mi][ni][3] + bb));
                        store_h16(xb, ra, nl, h[mi][ni][0], h[mi][ni][1]);
                        store_h16(xb, rb, nl, h[mi][ni][2], h[mi][ni][3]);
                    }
                }
            }
            BAR_HALF(barid);   // epilogue writes visible before next MMA
        } else {
            // ---- final epilogue: h = 0.5*(h+s2), output GEMV ----
            float* ybuf = (float*)(smem + SMEM_YBUF) + hf * 256;
            float p0s[8], p1s[8];
#pragma unroll
            for (int ni = 0; ni < 8; ni++) { p0s[ni] = 0.f; p1s[ni] = 0.f; }
#pragma unroll
            for (int mi = 0; mi < 2; mi++) {
                const int ra = f0 + 16 * mi + tg, rb = ra + 8;
                const float ba = __ldg(&b2[layer * FDIM + ra]);
                const float bb = __ldg(&b2[layer * FDIM + rb]);
                const float woa = __ldg(&W_out[ra]), wob = __ldg(&W_out[rb]);
#pragma unroll
                for (int ni = 0; ni < 8; ni++) {
                    float h0 = 0.5f * (h[mi][ni][0] + __sinf(OMEGA_W * (d[mi][ni][0] + ba)));
                    float h1 = 0.5f * (h[mi][ni][1] + __sinf(OMEGA_W * (d[mi][ni][1] + ba)));
                    float h2 = 0.5f * (h[mi][ni][2] + __sinf(OMEGA_W * (d[mi][ni][2] + bb)));
                    float h3 = 0.5f * (h[mi][ni][3] + __sinf(OMEGA_W * (d[mi][ni][3] + bb)));
                    p0s[ni] += fmaf(h0, woa, h2 * wob);
                    p1s[ni] += fmaf(h1, woa, h3 * wob);
                }
            }
#pragma unroll
            for (int ni = 0; ni < 8; ni++) {
                float p0 = p0s[ni], p1 = p1s[ni];
#pragma unroll
                for (int m = 4; m <= 16; m <<= 1) {
                    p0 += __shfl_xor_sync(0xffffffffu, p0, m);
                    p1 += __shfl_xor_sync(0xffffffffu, p1, m);
                }
                if (tg == 0) {
                    int nl = 8 * ni + t4 * 2;
                    *reinterpret_cast<float2*>(&ybuf[wm * 64 + nl]) = make_float2(p0, p1);
                }
            }
            BAR_HALF(barid);
        }
    }

    // ---- cross-warp output reduction (per half, 64 points) ----
    {
        const int lih = tid - hf * 128;
        if (lih < 64) {
            int p = n0 + lih;
            if (P0 + p < N) {
                float* ybuf = (float*)(smem + SMEM_YBUF) + hf * 256;
                float y = __ldg(&b_out[0]) + ybuf[lih] + ybuf[64 + lih]
                        + ybuf[128 + lih] + ybuf[192 + lih];
                out[P0 + p] = y;
            }
        }
    }
}

extern "C" void kernel_launch(void* const* d_in, const int* in_sizes, int n_in,
                              void* d_out, int out_size) {
    const float* coords  = (const float*)d_in[0];
    const float* W_first = (const float*)d_in[1];
    const float* b_first = (const float*)d_in[2];
    const float* W1      = (const float*)d_in[3];
    const float* b1      = (const float*)d_in[4];
    const float* W2      = (const float*)d_in[5];
    const float* b2      = (const float*)d_in[6];
    const float* W_out   = (const float*)d_in[7];
    const float* b_out   = (const float*)d_in[8];
    const int N = in_sizes[0] / 3;

    prep_weights_kernel<<<NGEMM, 256>>>(W1, W2);

    cudaFuncSetAttribute(siren_mma_kernel,
                         cudaFuncAttributeMaxDynamicSharedMemorySize, SMEM_TOTAL);

    const int nblocks = (N + TP - 1) / TP;
    siren_mma_kernel<<<nblocks, NTHR, SMEM_TOTAL>>>(coords, W_first, b_first,
                                                    b1, b2, W_out, b_out,
                                                    (float*)d_out, N);
}